// round 14
// baseline (speedup 1.0000x reference)
#include <cuda_runtime.h>
#include <cuda_fp16.h>
#include <cstdint>

#define BATCH 4
#define SEQ   2048
#define DIM   1024
#define HEADS 16
#define HD    64
#define ROWS (BATCH * SEQ)        // 8192

// Scratch (allocation-free rule: device globals), fp16 operand space
__device__ __half g_qkv[(size_t)ROWS * 3 * DIM];   // qkv, σ-permuted cols
__device__ __half g_att[(size_t)ROWS * DIM];       // attention out, σ-slot cols
__device__ __half g_xa[(size_t)ROWS * DIM];        // x, σ-permuted cols
__device__ __half g_wqkvT[(size_t)(3 * DIM) * DIM];// w_qkv^T, k+n σ-permuted
__device__ __half g_woutT[(size_t)DIM * DIM];      // w_out^T, k σ-permuted
__device__ float  g_bqkvp[3 * DIM];                // σ-permuted bias (fp32)

// ---------------------------------------------------------------------------
// helpers
// ---------------------------------------------------------------------------
__device__ __forceinline__ int sig16(int w) {          // w in [0,16)
    return 2 * (w >> 2) + (w & 1) + 8 * ((w >> 1) & 1);
}
__device__ __forceinline__ int sig(int s) { return (s & ~15) | sig16(s & 15); }

__device__ __forceinline__ void mma16(float* c, const uint32_t* a, const uint32_t* b) {
    asm volatile(
        "mma.sync.aligned.m16n8k16.row.col.f32.f16.f16.f32 "
        "{%0,%1,%2,%3}, {%4,%5,%6,%7}, {%8,%9}, {%0,%1,%2,%3};"
        : "+f"(c[0]), "+f"(c[1]), "+f"(c[2]), "+f"(c[3])
        : "r"(a[0]), "r"(a[1]), "r"(a[2]), "r"(a[3]), "r"(b[0]), "r"(b[1]));
}
__device__ __forceinline__ void ldmx4t(uint32_t* r, uint32_t addr) {
    asm volatile("ldmatrix.sync.aligned.m8n8.x4.trans.shared.b16 "
                 "{%0,%1,%2,%3}, [%4];"
                 : "=r"(r[0]), "=r"(r[1]), "=r"(r[2]), "=r"(r[3]) : "r"(addr));
}
__device__ __forceinline__ uint32_t h2exp2(uint32_t x) {
    uint32_t r;
    asm("ex2.approx.f16x2 %0, %1;" : "=r"(r) : "r"(x));
    return r;
}
__device__ __forceinline__ uint32_t sptr(const void* p) {
    return (uint32_t)__cvta_generic_to_shared(p);
}
__device__ __forceinline__ void cp16(uint32_t s, const void* g) {
    asm volatile("cp.async.ca.shared.global [%0], [%1], 16;" :: "r"(s), "l"(g));
}
#define CP_COMMIT() asm volatile("cp.async.commit_group;")
#define CP_WAIT0()  asm volatile("cp.async.wait_group 0;")
#define CP_WAIT1()  asm volatile("cp.async.wait_group 1;")

// ---------------------------------------------------------------------------
// Fused pre-pass kernel (unchanged)
// ---------------------------------------------------------------------------
__device__ __forceinline__ void prep_w_tile(const float* __restrict__ src,
                                            __half* __restrict__ dst,
                                            int N, int kb, int nb, bool permn,
                                            int tid) {
    __shared__ float tile[32][33];
    const int tx = tid & 15, ty = tid >> 4;
    tile[ty][tx]           = src[(size_t)(kb + ty) * N + nb + tx];
    tile[ty][tx + 16]      = src[(size_t)(kb + ty) * N + nb + tx + 16];
    tile[ty + 16][tx]      = src[(size_t)(kb + ty + 16) * N + nb + tx];
    tile[ty + 16][tx + 16] = src[(size_t)(kb + ty + 16) * N + nb + tx + 16];
    __syncthreads();
    const int s  = 2 * tx;
    const int t0 = (s & 16) | sig16(s & 15);
    #pragma unroll
    for (int i = 0; i < 2; i++) {
        const int ny = ty + 16 * i;
        const int nn = permn ? ((ny & ~15) | sig16(ny & 15)) : ny;
        __half2 h = __floats2half2_rn(tile[t0][nn], tile[t0 + 1][nn]);
        *(__half2*)&dst[(size_t)(nb + ny) * DIM + kb + s] = h;
    }
}

__global__ __launch_bounds__(256)
void prep_all(const float* __restrict__ x, const float* __restrict__ wq,
              const float* __restrict__ wo, const float* __restrict__ bq) {
    const int bid = blockIdx.x;
    const int tid = threadIdx.x;
    if (bid < 2048) {
        const size_t base = ((size_t)bid * 256 + tid) * 16;
        float v[16];
        #pragma unroll
        for (int i = 0; i < 16; i += 4) *(float4*)&v[i] = *(const float4*)&x[base + i];
        __half2 h[8];
        #pragma unroll
        for (int u = 0; u < 4; u++) {
            h[2 * u]     = __floats2half2_rn(v[2 * u],     v[2 * u + 1]);
            h[2 * u + 1] = __floats2half2_rn(v[2 * u + 8], v[2 * u + 9]);
        }
        *(uint4*)&g_xa[base]     = *(uint4*)&h[0];
        *(uint4*)&g_xa[base + 8] = *(uint4*)&h[4];
        if (bid < 12) {
            const int s = bid * 256 + tid;
            g_bqkvp[s] = bq[sig(s)];
        }
    } else if (bid < 2048 + 3072) {
        const int b2 = bid - 2048;
        prep_w_tile(wq, g_wqkvT, 3 * DIM, (b2 & 31) * 32, (b2 >> 5) * 32, true, tid);
    } else {
        const int b3 = bid - 5120;
        prep_w_tile(wo, g_woutT, DIM, (b3 & 31) * 32, (b3 >> 5) * 32, false, tid);
    }
}

// ---------------------------------------------------------------------------
// FP16 MMA GEMM v7: block 128x128, BK=64, 128 thr (4 warps 2x2), warp 64x64.
// 2 CTAs/SM. Fragment-level double buffering (load ks+1 while ks MMAs issue).
// ---------------------------------------------------------------------------
#define GKW 80
#define GA_H (128 * GKW)
#define GSTG_H (2 * GA_H)
#define GEMM_SMEM (2 * GSTG_H * 2)          // 81920 B

__device__ __forceinline__ void gemm_load(__half* stage,
                                          const __half* __restrict__ A,
                                          const __half* __restrict__ B,
                                          int bm, int bn, int k0, int tid) {
    #pragma unroll
    for (int i = 0; i < 8; i++) {
        int t = tid + i * 128;              // 0..1023
        int row = t >> 3, c = t & 7;
        cp16(sptr(stage + row * GKW + c * 8), A + (size_t)(bm + row) * DIM + k0 + c * 8);
        cp16(sptr(stage + GA_H + row * GKW + c * 8), B + (size_t)(bn + row) * DIM + k0 + c * 8);
    }
}

template<bool HALF_OUT>
__global__ __launch_bounds__(128, 2)
void hgemm(const __half* __restrict__ A, const __half* __restrict__ B,
           const float* __restrict__ bias, void* __restrict__ Cv, int N) {
    extern __shared__ __half smh[];
    const int tid  = threadIdx.x;
    const int lane = tid & 31;
    const int wid  = tid >> 5;
    const int g    = lane >> 2;
    const int tig  = lane & 3;
    const int wm   = wid >> 1;          // 0..1
    const int wn   = wid & 1;           // 0..1
    const int bm   = blockIdx.y * 128;
    const int bn   = blockIdx.x * 128;

    float acc[4][8][4];
    #pragma unroll
    for (int mi = 0; mi < 4; mi++)
        #pragma unroll
        for (int ni = 0; ni < 8; ni++)
            #pragma unroll
            for (int j = 0; j < 4; j++) acc[mi][ni][j] = 0.f;

    constexpr int NT = DIM / 64;        // 16 k-tiles

    uint32_t afr[2][4][4], bfr[2][8][2];

    auto load_frag = [&](int buf, const __half* As, const __half* Bs, int ks) {
        const int co = ks * 16 + 4 * tig;
        #pragma unroll
        for (int mi = 0; mi < 4; mi++) {
            const int m = wm * 64 + mi * 16 + g;
            uint2 lo = *(const uint2*)&As[m * GKW + co];
            uint2 hi = *(const uint2*)&As[(m + 8) * GKW + co];
            afr[buf][mi][0] = lo.x; afr[buf][mi][2] = lo.y;
            afr[buf][mi][1] = hi.x; afr[buf][mi][3] = hi.y;
        }
        #pragma unroll
        for (int ni = 0; ni < 8; ni++) {
            const int n = wn * 64 + ni * 8 + g;
            uint2 bb = *(const uint2*)&Bs[n * GKW + co];
            bfr[buf][ni][0] = bb.x; bfr[buf][ni][1] = bb.y;
        }
    };

    gemm_load(smh, A, B, bm, bn, 0, tid);
    CP_COMMIT();

    for (int t = 0; t < NT; t++) {
        CP_WAIT0();
        __syncthreads();
        if (t + 1 < NT) {
            gemm_load(smh + ((t + 1) & 1) * GSTG_H, A, B, bm, bn, (t + 1) * 64, tid);
            CP_COMMIT();
        }
        const __half* As = smh + (t & 1) * GSTG_H;
        const __half* Bs = As + GA_H;

        load_frag(0, As, Bs, 0);
        #pragma unroll
        for (int ks = 0; ks < 4; ks++) {
            if (ks < 3) load_frag((ks + 1) & 1, As, Bs, ks + 1);
            const int cur = ks & 1;
            #pragma unroll
            for (int mi = 0; mi < 4; mi++)
                #pragma unroll
                for (int ni = 0; ni < 8; ni++)
                    mma16(acc[mi][ni], afr[cur][mi], bfr[cur][ni]);
        }
    }

    #pragma unroll
    for (int mi = 0; mi < 4; mi++) {
        const int r0 = bm + wm * 64 + mi * 16 + g;
        #pragma unroll
        for (int ni = 0; ni < 8; ni++) {
            const int col = bn + wn * 64 + ni * 8 + 2 * tig;
            const float b0 = bias[col], b1 = bias[col + 1];
            const float v00 = acc[mi][ni][0] + b0, v01 = acc[mi][ni][1] + b1;
            const float v10 = acc[mi][ni][2] + b0, v11 = acc[mi][ni][3] + b1;
            if (HALF_OUT) {
                __half* C = (__half*)Cv;
                *(__half2*)&C[(size_t)r0 * N + col]       = __floats2half2_rn(v00, v01);
                *(__half2*)&C[(size_t)(r0 + 8) * N + col] = __floats2half2_rn(v10, v11);
            } else {
                float* C = (float*)Cv;
                *(float2*)&C[(size_t)r0 * N + col]       = make_float2(v00, v01);
                *(float2*)&C[(size_t)(r0 + 8) * N + col] = make_float2(v10, v11);
            }
        }
    }
}

// ---------------------------------------------------------------------------
// FP16 MMA causal flash attention v8.
// Log2-domain softmax, ex2.approx.f16x2 P, l via ones-B MMA.
// 3-stage cp.async KV ring (two tiles in flight), 2 CTAs/SM.
// smem halves: K[3][64][80] | V[3][64][72]  (58368 B)
// ---------------------------------------------------------------------------
#define AQT 128
#define KW  80
#define VW  72
#define KT_H (64 * KW)
#define VT_H (64 * VW)
#define NSTG 3
#define ATTN_SMEM ((NSTG * KT_H + NSTG * VT_H) * 2)   // 58368 B

__device__ __forceinline__ void attn_load_kv(__half* Ks, __half* Vs,
                                             int b, int h, int kt, int tid) {
    const size_t base = ((size_t)(b * SEQ + kt * 64)) * (3 * DIM) + DIM + h * HD;
    #pragma unroll
    for (int i = 0; i < 4; i++) {
        int t = tid + i * 128;              // 0..511
        int row = t >> 3, c = t & 7;
        const __half* src = &g_qkv[base + (size_t)row * 3 * DIM + c * 8];
        cp16(sptr(Ks + row * KW + c * 8), src);
        cp16(sptr(Vs + row * VW + c * 8), src + DIM);
    }
}

__global__ __launch_bounds__(128)
void attn_fp16() {
    extern __shared__ __half smh[];
    __half* Kb[NSTG];
    __half* Vb[NSTG];
    #pragma unroll
    for (int i = 0; i < NSTG; i++) {
        Kb[i] = smh + i * KT_H;
        Vb[i] = smh + NSTG * KT_H + i * VT_H;
    }

    const int qt   = gridDim.x - 1 - blockIdx.x;   // longest-first scheduling
    const int h    = blockIdx.y;
    const int b    = blockIdx.z;
    const int tid  = threadIdx.x;
    const int lane = tid & 31;
    const int wid  = tid >> 5;
    const int g    = lane >> 2;
    const int tig  = lane & 3;

    const int qr  = qt * AQT + wid * 32;
    const int nkt = qt * 2 + 2;

    attn_load_kv(Kb[0], Vb[0], b, h, 0, tid);
    CP_COMMIT();
    if (nkt > 1) {
        attn_load_kv(Kb[1], Vb[1], b, h, 1, tid);
        CP_COMMIT();
    }

    // q scale folds 1/sqrt(64) AND log2(e): softmax runs in base-2 domain
    const __half2 qsc = __float2half2_rn(0.125f * 1.44269504f);
    uint32_t qf[2][4][4];
    #pragma unroll
    for (int s = 0; s < 2; s++) {
        const size_t r0 = ((size_t)(b * SEQ + qr + s * 16 + g)) * (3 * DIM) + h * HD;
        const size_t r1 = r0 + (size_t)8 * 3 * DIM;
        #pragma unroll
        for (int ks = 0; ks < 4; ks++) {
            uint2 lo = *(const uint2*)&g_qkv[r0 + ks * 16 + 4 * tig];
            uint2 hi = *(const uint2*)&g_qkv[r1 + ks * 16 + 4 * tig];
            __half2 t;
            t = __hmul2(*(__half2*)&lo.x, qsc); qf[s][ks][0] = *(uint32_t*)&t;
            t = __hmul2(*(__half2*)&hi.x, qsc); qf[s][ks][1] = *(uint32_t*)&t;
            t = __hmul2(*(__half2*)&lo.y, qsc); qf[s][ks][2] = *(uint32_t*)&t;
            t = __hmul2(*(__half2*)&hi.y, qsc); qf[s][ks][3] = *(uint32_t*)&t;
        }
    }

    float oacc[2][8][4];
    #pragma unroll
    for (int s = 0; s < 2; s++)
        #pragma unroll
        for (int ni = 0; ni < 8; ni++)
            #pragma unroll
            for (int j = 0; j < 4; j++) oacc[s][ni][j] = 0.f;
    float mm[2][2] = {{-1e30f, -1e30f}, {-1e30f, -1e30f}};
    float ll[2][2] = {{0.f, 0.f}, {0.f, 0.f}};
    const uint32_t ones2 = 0x3C003C00u;            // half2(1,1)
    const uint32_t onesb[2] = { ones2, ones2 };

    for (int kt = 0; kt < nkt; kt++) {
        if (kt + 1 < nkt) { CP_WAIT1(); } else { CP_WAIT0(); }
        __syncthreads();
        if (kt + 2 < nkt) {
            const int st = (kt + 2) % NSTG;
            attn_load_kv(Kb[st], Vb[st], b, h, kt + 2, tid);
            CP_COMMIT();
        }
        const __half* Ks = Kb[kt % NSTG];
        const __half* Vs = Vb[kt % NSTG];

        const bool active = (kt * 64 <= qr + 31);
        if (active) {
            const bool diag = ((kt + 1) * 64 > qr);

            // ---- S = Q K^T (log2-e domain): K frags shared by both subtiles
            float sacc[2][8][4];
            #pragma unroll
            for (int s = 0; s < 2; s++)
                #pragma unroll
                for (int ni = 0; ni < 8; ni++)
                    #pragma unroll
                    for (int j = 0; j < 4; j++) sacc[s][ni][j] = 0.f;

            #pragma unroll
            for (int ks = 0; ks < 4; ks++) {
                const int co = ks * 16 + 4 * tig;
                #pragma unroll
                for (int ni = 0; ni < 8; ni++) {
                    uint2 bb = *(const uint2*)&Ks[(ni * 8 + g) * KW + co];
                    uint32_t bfr[2] = { bb.x, bb.y };
                    mma16(sacc[0][ni], qf[0][ks], bfr);
                    mma16(sacc[1][ni], qf[1][ks], bfr);
                }
            }

            // ---- per-subtile: mask, max, P = ex2(S-m) in fp16x2, l via MMA
            uint32_t pa[2][4][4];
            #pragma unroll
            for (int s = 0; s < 2; s++) {
                const int rA = qr + s * 16 + g, rB = rA + 8;
                if (diag) {
                    #pragma unroll
                    for (int ni = 0; ni < 8; ni++) {
                        const int c0 = kt * 64 + ni * 8 + 2 * tig;
                        if (c0 > rA)     sacc[s][ni][0] = -1e30f;
                        if (c0 + 1 > rA) sacc[s][ni][1] = -1e30f;
                        if (c0 > rB)     sacc[s][ni][2] = -1e30f;
                        if (c0 + 1 > rB) sacc[s][ni][3] = -1e30f;
                    }
                }

                float t0 = -1e30f, t1 = -1e30f;
                #pragma unroll
                for (int ni = 0; ni < 8; ni++) {
                    t0 = fmaxf(t0, fmaxf(sacc[s][ni][0], sacc[s][ni][1]));
                    t1 = fmaxf(t1, fmaxf(sacc[s][ni][2], sacc[s][ni][3]));
                }
                t0 = fmaxf(t0, __shfl_xor_sync(0xffffffffu, t0, 1));
                t0 = fmaxf(t0, __shfl_xor_sync(0xffffffffu, t0, 2));
                t1 = fmaxf(t1, __shfl_xor_sync(0xffffffffu, t1, 1));
                t1 = fmaxf(t1, __shfl_xor_sync(0xffffffffu, t1, 2));

                const float nm0 = fmaxf(mm[s][0], t0), nm1 = fmaxf(mm[s][1], t1);
                const float cr0 = exp2f(mm[s][0] - nm0), cr1 = exp2f(mm[s][1] - nm1);
                ll[s][0] *= cr0; ll[s][1] *= cr1;
                #pragma unroll
                for (int ni = 0; ni < 8; ni++) {
                    oacc[s][ni][0] *= cr0; oacc[s][ni][1] *= cr0;
                    oacc[s][ni][2] *= cr1; oacc[s][ni][3] *= cr1;
                }

                #pragma unroll
                for (int ks = 0; ks < 4; ks++) {
                    const int n0 = 2 * ks, n1 = 2 * ks + 1;
                    __half2 d;
                    d = __floats2half2_rn(sacc[s][n0][0] - nm0, sacc[s][n0][1] - nm0);
                    pa[s][ks][0] = h2exp2(*(uint32_t*)&d);
                    d = __floats2half2_rn(sacc[s][n0][2] - nm1, sacc[s][n0][3] - nm1);
                    pa[s][ks][1] = h2exp2(*(uint32_t*)&d);
                    d = __floats2half2_rn(sacc[s][n1][0] - nm0, sacc[s][n1][1] - nm0);
                    pa[s][ks][2] = h2exp2(*(uint32_t*)&d);
                    d = __floats2half2_rn(sacc[s][n1][2] - nm1, sacc[s][n1][3] - nm1);
                    pa[s][ks][3] = h2exp2(*(uint32_t*)&d);
                }

                // l += P @ ones  (fp32 accum)
                float lacc[4] = {0.f, 0.f, 0.f, 0.f};
                #pragma unroll
                for (int ks = 0; ks < 4; ks++) mma16(lacc, pa[s][ks], onesb);
                ll[s][0] += lacc[0];
                ll[s][1] += lacc[2];
                mm[s][0] = nm0; mm[s][1] = nm1;
            }

            // ---- O += P @ V ----
            const int lt = lane >> 3, lr = lane & 7;
            #pragma unroll
            for (int ks = 0; ks < 4; ks++) {
                uint32_t vb[4][4];
                const int vrow = ks * 16 + (lt & 1) * 8 + lr;
                const int vcb  = (lt >> 1) * 8;
                #pragma unroll
                for (int d4 = 0; d4 < 4; d4++)
                    ldmx4t(vb[d4], sptr(Vs + vrow * VW + vcb + d4 * 16));
                #pragma unroll
                for (int s = 0; s < 2; s++) {
                    #pragma unroll
                    for (int d4 = 0; d4 < 4; d4++) {
                        mma16(oacc[s][2 * d4],     pa[s][ks], &vb[d4][0]);
                        mma16(oacc[s][2 * d4 + 1], pa[s][ks], &vb[d4][2]);
                    }
                }
            }
        }
    }

    // ---- epilogue: O/l -> g_att (fp16, σ-slot cols) ----
    #pragma unroll
    for (int s = 0; s < 2; s++) {
        const float inv0 = 1.f / ll[s][0], inv1 = 1.f / ll[s][1];
        const size_t ob = ((size_t)(b * SEQ + qr + s * 16 + g)) * DIM + h * HD;
        #pragma unroll
        for (int ni = 0; ni < 8; ni++) {
            const int c = ni * 8 + 2 * tig;
            *(__half2*)&g_att[ob + c] =
                __floats2half2_rn(oacc[s][ni][0] * inv0, oacc[s][ni][1] * inv0);
            *(__half2*)&g_att[ob + (size_t)8 * DIM + c] =
                __floats2half2_rn(oacc[s][ni][2] * inv1, oacc[s][ni][3] * inv1);
        }
    }
}

// ---------------------------------------------------------------------------
extern "C" void kernel_launch(void* const* d_in, const int* in_sizes, int n_in,
                              void* d_out, int out_size) {
    const float* x     = (const float*)d_in[0];
    const float* w_qkv = (const float*)d_in[1];
    const float* b_qkv = (const float*)d_in[2];
    const float* w_out = (const float*)d_in[3];
    const float* b_out = (const float*)d_in[4];
    float* out = (float*)d_out;

    __half* qkv; cudaGetSymbolAddress((void**)&qkv, g_qkv);
    __half* att; cudaGetSymbolAddress((void**)&att, g_att);
    __half* xa;  cudaGetSymbolAddress((void**)&xa,  g_xa);
    __half* wqT; cudaGetSymbolAddress((void**)&wqT, g_wqkvT);
    __half* woT; cudaGetSymbolAddress((void**)&woT, g_woutT);
    float*  bqp; cudaGetSymbolAddress((void**)&bqp, g_bqkvp);

    cudaFuncSetAttribute(hgemm<true>,
                         cudaFuncAttributeMaxDynamicSharedMemorySize, GEMM_SMEM);
    cudaFuncSetAttribute(hgemm<false>,
                         cudaFuncAttributeMaxDynamicSharedMemorySize, GEMM_SMEM);
    cudaFuncSetAttribute(attn_fp16,
                         cudaFuncAttributeMaxDynamicSharedMemorySize, ATTN_SMEM);

    // --- fused pre-pass ---
    prep_all<<<6144, 256>>>(x, w_qkv, w_out, b_qkv);

    // 1) QKV projection (fp16 mma, frag-pipelined, 2 CTAs/SM)
    {
        dim3 grid(3 * DIM / 128, ROWS / 128);
        hgemm<true><<<grid, 128, GEMM_SMEM>>>(xa, wqT, bqp, qkv, 3 * DIM);
    }
    // 2) causal multi-head attention (3-stage KV ring)
    {
        dim3 grid(SEQ / AQT, HEADS, BATCH);
        attn_fp16<<<grid, 128, ATTN_SMEM>>>();
    }
    // 3) output projection
    {
        dim3 grid(DIM / 128, ROWS / 128);
        hgemm<false><<<grid, 128, GEMM_SMEM>>>(att, woT, b_out, out, DIM);
    }
}

// round 15
// speedup vs baseline: 1.0159x; 1.0159x over previous
#include <cuda_runtime.h>
#include <cuda_fp16.h>
#include <cstdint>

#define BATCH 4
#define SEQ   2048
#define DIM   1024
#define HEADS 16
#define HD    64
#define ROWS (BATCH * SEQ)        // 8192

// Scratch (allocation-free rule: device globals), fp16 operand space
__device__ __half g_qkv[(size_t)ROWS * 3 * DIM];   // qkv, σ-permuted cols
__device__ __half g_att[(size_t)ROWS * DIM];       // attention out, σ-slot cols
__device__ __half g_xa[(size_t)ROWS * DIM];        // x, σ-permuted cols
__device__ __half g_wqkvT[(size_t)(3 * DIM) * DIM];// w_qkv^T, k+n σ-permuted
__device__ __half g_woutT[(size_t)DIM * DIM];      // w_out^T, k σ-permuted
__device__ float  g_bqkvp[3 * DIM];                // σ-permuted bias (fp32)

// ---------------------------------------------------------------------------
// helpers
// ---------------------------------------------------------------------------
__device__ __forceinline__ int sig16(int w) {          // w in [0,16)
    return 2 * (w >> 2) + (w & 1) + 8 * ((w >> 1) & 1);
}
__device__ __forceinline__ int sig(int s) { return (s & ~15) | sig16(s & 15); }

__device__ __forceinline__ void mma16(float* c, const uint32_t* a, const uint32_t* b) {
    asm volatile(
        "mma.sync.aligned.m16n8k16.row.col.f32.f16.f16.f32 "
        "{%0,%1,%2,%3}, {%4,%5,%6,%7}, {%8,%9}, {%0,%1,%2,%3};"
        : "+f"(c[0]), "+f"(c[1]), "+f"(c[2]), "+f"(c[3])
        : "r"(a[0]), "r"(a[1]), "r"(a[2]), "r"(a[3]), "r"(b[0]), "r"(b[1]));
}
__device__ __forceinline__ void ldmx4t(uint32_t* r, uint32_t addr) {
    asm volatile("ldmatrix.sync.aligned.m8n8.x4.trans.shared.b16 "
                 "{%0,%1,%2,%3}, [%4];"
                 : "=r"(r[0]), "=r"(r[1]), "=r"(r[2]), "=r"(r[3]) : "r"(addr));
}
__device__ __forceinline__ uint32_t h2exp2(uint32_t x) {
    uint32_t r;
    asm("ex2.approx.f16x2 %0, %1;" : "=r"(r) : "r"(x));
    return r;
}
__device__ __forceinline__ uint32_t sptr(const void* p) {
    return (uint32_t)__cvta_generic_to_shared(p);
}
__device__ __forceinline__ void cp16(uint32_t s, const void* g) {
    asm volatile("cp.async.ca.shared.global [%0], [%1], 16;" :: "r"(s), "l"(g));
}
#define CP_COMMIT() asm volatile("cp.async.commit_group;")
#define CP_WAIT0()  asm volatile("cp.async.wait_group 0;")

// ---------------------------------------------------------------------------
// Fused pre-pass kernel
// ---------------------------------------------------------------------------
__device__ __forceinline__ void prep_w_tile(const float* __restrict__ src,
                                            __half* __restrict__ dst,
                                            int N, int kb, int nb, bool permn,
                                            int tid) {
    __shared__ float tile[32][33];
    const int tx = tid & 15, ty = tid >> 4;
    tile[ty][tx]           = src[(size_t)(kb + ty) * N + nb + tx];
    tile[ty][tx + 16]      = src[(size_t)(kb + ty) * N + nb + tx + 16];
    tile[ty + 16][tx]      = src[(size_t)(kb + ty + 16) * N + nb + tx];
    tile[ty + 16][tx + 16] = src[(size_t)(kb + ty + 16) * N + nb + tx + 16];
    __syncthreads();
    const int s  = 2 * tx;
    const int t0 = (s & 16) | sig16(s & 15);
    #pragma unroll
    for (int i = 0; i < 2; i++) {
        const int ny = ty + 16 * i;
        const int nn = permn ? ((ny & ~15) | sig16(ny & 15)) : ny;
        __half2 h = __floats2half2_rn(tile[t0][nn], tile[t0 + 1][nn]);
        *(__half2*)&dst[(size_t)(nb + ny) * DIM + kb + s] = h;
    }
}

__global__ __launch_bounds__(256)
void prep_all(const float* __restrict__ x, const float* __restrict__ wq,
              const float* __restrict__ wo, const float* __restrict__ bq) {
    const int bid = blockIdx.x;
    const int tid = threadIdx.x;
    if (bid < 2048) {
        const size_t base = ((size_t)bid * 256 + tid) * 16;
        float v[16];
        #pragma unroll
        for (int i = 0; i < 16; i += 4) *(float4*)&v[i] = *(const float4*)&x[base + i];
        __half2 h[8];
        #pragma unroll
        for (int u = 0; u < 4; u++) {
            h[2 * u]     = __floats2half2_rn(v[2 * u],     v[2 * u + 1]);
            h[2 * u + 1] = __floats2half2_rn(v[2 * u + 8], v[2 * u + 9]);
        }
        *(uint4*)&g_xa[base]     = *(uint4*)&h[0];
        *(uint4*)&g_xa[base + 8] = *(uint4*)&h[4];
        if (bid < 12) {
            const int s = bid * 256 + tid;
            g_bqkvp[s] = bq[sig(s)];
        }
    } else if (bid < 2048 + 3072) {
        const int b2 = bid - 2048;
        prep_w_tile(wq, g_wqkvT, 3 * DIM, (b2 & 31) * 32, (b2 >> 5) * 32, true, tid);
    } else {
        const int b3 = bid - 5120;
        prep_w_tile(wo, g_woutT, DIM, (b3 & 31) * 32, (b3 >> 5) * 32, false, tid);
    }
}

// ---------------------------------------------------------------------------
// FP16 MMA GEMM (R12 config): block 128x128, BK=64, 128 thr (4 warps 2x2),
// warp 64x64. 2 CTAs/SM. 1 barrier per k-tile.
// ---------------------------------------------------------------------------
#define GKW 80
#define GA_H (128 * GKW)
#define GSTG_H (2 * GA_H)
#define GEMM_SMEM (2 * GSTG_H * 2)          // 81920 B

__device__ __forceinline__ void gemm_load(__half* stage,
                                          const __half* __restrict__ A,
                                          const __half* __restrict__ B,
                                          int bm, int bn, int k0, int tid) {
    #pragma unroll
    for (int i = 0; i < 8; i++) {
        int t = tid + i * 128;              // 0..1023
        int row = t >> 3, c = t & 7;
        cp16(sptr(stage + row * GKW + c * 8), A + (size_t)(bm + row) * DIM + k0 + c * 8);
        cp16(sptr(stage + GA_H + row * GKW + c * 8), B + (size_t)(bn + row) * DIM + k0 + c * 8);
    }
}

template<bool HALF_OUT>
__global__ __launch_bounds__(128, 2)
void hgemm(const __half* __restrict__ A, const __half* __restrict__ B,
           const float* __restrict__ bias, void* __restrict__ Cv, int N) {
    extern __shared__ __half smh[];
    const int tid  = threadIdx.x;
    const int lane = tid & 31;
    const int wid  = tid >> 5;
    const int g    = lane >> 2;
    const int tig  = lane & 3;
    const int wm   = wid >> 1;          // 0..1
    const int wn   = wid & 1;           // 0..1
    const int bm   = blockIdx.y * 128;
    const int bn   = blockIdx.x * 128;

    float acc[4][8][4];
    #pragma unroll
    for (int mi = 0; mi < 4; mi++)
        #pragma unroll
        for (int ni = 0; ni < 8; ni++)
            #pragma unroll
            for (int j = 0; j < 4; j++) acc[mi][ni][j] = 0.f;

    constexpr int NT = DIM / 64;        // 16 k-tiles

    gemm_load(smh, A, B, bm, bn, 0, tid);
    CP_COMMIT();

    for (int t = 0; t < NT; t++) {
        CP_WAIT0();
        __syncthreads();
        if (t + 1 < NT) {
            gemm_load(smh + ((t + 1) & 1) * GSTG_H, A, B, bm, bn, (t + 1) * 64, tid);
            CP_COMMIT();
        }
        const __half* As = smh + (t & 1) * GSTG_H;
        const __half* Bs = As + GA_H;

        #pragma unroll
        for (int ks = 0; ks < 4; ks++) {
            const int co = ks * 16 + 4 * tig;
            uint32_t a[4][4], b[8][2];
            #pragma unroll
            for (int mi = 0; mi < 4; mi++) {
                const int m = wm * 64 + mi * 16 + g;
                uint2 lo = *(const uint2*)&As[m * GKW + co];
                uint2 hi = *(const uint2*)&As[(m + 8) * GKW + co];
                a[mi][0] = lo.x; a[mi][2] = lo.y;
                a[mi][1] = hi.x; a[mi][3] = hi.y;
            }
            #pragma unroll
            for (int ni = 0; ni < 8; ni++) {
                const int n = wn * 64 + ni * 8 + g;
                uint2 bb = *(const uint2*)&Bs[n * GKW + co];
                b[ni][0] = bb.x; b[ni][1] = bb.y;
            }
            #pragma unroll
            for (int mi = 0; mi < 4; mi++)
                #pragma unroll
                for (int ni = 0; ni < 8; ni++)
                    mma16(acc[mi][ni], a[mi], b[ni]);
        }
    }

    #pragma unroll
    for (int mi = 0; mi < 4; mi++) {
        const int r0 = bm + wm * 64 + mi * 16 + g;
        #pragma unroll
        for (int ni = 0; ni < 8; ni++) {
            const int col = bn + wn * 64 + ni * 8 + 2 * tig;
            const float b0 = bias[col], b1 = bias[col + 1];
            const float v00 = acc[mi][ni][0] + b0, v01 = acc[mi][ni][1] + b1;
            const float v10 = acc[mi][ni][2] + b0, v11 = acc[mi][ni][3] + b1;
            if (HALF_OUT) {
                __half* C = (__half*)Cv;
                *(__half2*)&C[(size_t)r0 * N + col]       = __floats2half2_rn(v00, v01);
                *(__half2*)&C[(size_t)(r0 + 8) * N + col] = __floats2half2_rn(v10, v11);
            } else {
                float* C = (float*)Cv;
                *(float2*)&C[(size_t)r0 * N + col]       = make_float2(v00, v01);
                *(float2*)&C[(size_t)(r0 + 8) * N + col] = make_float2(v10, v11);
            }
        }
    }
}

// ---------------------------------------------------------------------------
// FP16 MMA causal flash attention (R12 + interleaved max-shuffle chains).
// Log2-domain softmax, ex2.approx.f16x2 P, l via ones-B MMA.
// grid = (SEQ/128, HEADS, BATCH), 128 thr, warp = 32 q rows, 2 CTAs/SM.
// smem halves: K[2][64][80] | V[2][64][72]  (38912 B)
// ---------------------------------------------------------------------------
#define AQT 128
#define KW  80
#define VW  72
#define KT_H (64 * KW)
#define VT_H (64 * VW)
#define ATTN_SMEM ((2 * KT_H + 2 * VT_H) * 2)   // 38912 B

__device__ __forceinline__ void attn_load_kv(__half* Ks, __half* Vs,
                                             int b, int h, int kt, int tid) {
    const size_t base = ((size_t)(b * SEQ + kt * 64)) * (3 * DIM) + DIM + h * HD;
    #pragma unroll
    for (int i = 0; i < 4; i++) {
        int t = tid + i * 128;              // 0..511
        int row = t >> 3, c = t & 7;
        const __half* src = &g_qkv[base + (size_t)row * 3 * DIM + c * 8];
        cp16(sptr(Ks + row * KW + c * 8), src);
        cp16(sptr(Vs + row * VW + c * 8), src + DIM);
    }
}

__global__ __launch_bounds__(128)
void attn_fp16() {
    extern __shared__ __half smh[];
    __half* Kb[2] = { smh, smh + KT_H };
    __half* Vb[2] = { smh + 2 * KT_H, smh + 2 * KT_H + VT_H };

    const int qt   = gridDim.x - 1 - blockIdx.x;   // longest-first scheduling
    const int h    = blockIdx.y;
    const int b    = blockIdx.z;
    const int tid  = threadIdx.x;
    const int lane = tid & 31;
    const int wid  = tid >> 5;
    const int g    = lane >> 2;
    const int tig  = lane & 3;

    const int qr  = qt * AQT + wid * 32;
    const int nkt = qt * 2 + 2;

    attn_load_kv(Kb[0], Vb[0], b, h, 0, tid);
    CP_COMMIT();

    // q scale folds 1/sqrt(64) AND log2(e): softmax runs in base-2 domain
    const __half2 qsc = __float2half2_rn(0.125f * 1.44269504f);
    uint32_t qf[2][4][4];
    #pragma unroll
    for (int s = 0; s < 2; s++) {
        const size_t r0 = ((size_t)(b * SEQ + qr + s * 16 + g)) * (3 * DIM) + h * HD;
        const size_t r1 = r0 + (size_t)8 * 3 * DIM;
        #pragma unroll
        for (int ks = 0; ks < 4; ks++) {
            uint2 lo = *(const uint2*)&g_qkv[r0 + ks * 16 + 4 * tig];
            uint2 hi = *(const uint2*)&g_qkv[r1 + ks * 16 + 4 * tig];
            __half2 t;
            t = __hmul2(*(__half2*)&lo.x, qsc); qf[s][ks][0] = *(uint32_t*)&t;
            t = __hmul2(*(__half2*)&hi.x, qsc); qf[s][ks][1] = *(uint32_t*)&t;
            t = __hmul2(*(__half2*)&lo.y, qsc); qf[s][ks][2] = *(uint32_t*)&t;
            t = __hmul2(*(__half2*)&hi.y, qsc); qf[s][ks][3] = *(uint32_t*)&t;
        }
    }

    float oacc[2][8][4];
    #pragma unroll
    for (int s = 0; s < 2; s++)
        #pragma unroll
        for (int ni = 0; ni < 8; ni++)
            #pragma unroll
            for (int j = 0; j < 4; j++) oacc[s][ni][j] = 0.f;
    float mm[2][2] = {{-1e30f, -1e30f}, {-1e30f, -1e30f}};
    float ll[2][2] = {{0.f, 0.f}, {0.f, 0.f}};
    const uint32_t ones2 = 0x3C003C00u;            // half2(1,1)
    const uint32_t onesb[2] = { ones2, ones2 };

    for (int kt = 0; kt < nkt; kt++) {
        CP_WAIT0();
        __syncthreads();
        if (kt + 1 < nkt) {
            attn_load_kv(Kb[(kt + 1) & 1], Vb[(kt + 1) & 1], b, h, kt + 1, tid);
            CP_COMMIT();
        }
        const __half* Ks = Kb[kt & 1];
        const __half* Vs = Vb[kt & 1];

        const bool active = (kt * 64 <= qr + 31);
        if (active) {
            const bool diag = ((kt + 1) * 64 > qr);

            // ---- S = Q K^T (log2-e domain): K frags shared by both subtiles
            float sacc[2][8][4];
            #pragma unroll
            for (int s = 0; s < 2; s++)
                #pragma unroll
                for (int ni = 0; ni < 8; ni++)
                    #pragma unroll
                    for (int j = 0; j < 4; j++) sacc[s][ni][j] = 0.f;

            #pragma unroll
            for (int ks = 0; ks < 4; ks++) {
                const int co = ks * 16 + 4 * tig;
                #pragma unroll
                for (int ni = 0; ni < 8; ni++) {
                    uint2 bb = *(const uint2*)&Ks[(ni * 8 + g) * KW + co];
                    uint32_t bfr[2] = { bb.x, bb.y };
                    mma16(sacc[0][ni], qf[0][ks], bfr);
                    mma16(sacc[1][ni], qf[1][ks], bfr);
                }
            }

            // ---- mask + local maxes for BOTH subtiles ----
            float tmx[2][2];
            #pragma unroll
            for (int s = 0; s < 2; s++) {
                const int rA = qr + s * 16 + g, rB = rA + 8;
                if (diag) {
                    #pragma unroll
                    for (int ni = 0; ni < 8; ni++) {
                        const int c0 = kt * 64 + ni * 8 + 2 * tig;
                        if (c0 > rA)     sacc[s][ni][0] = -1e30f;
                        if (c0 + 1 > rA) sacc[s][ni][1] = -1e30f;
                        if (c0 > rB)     sacc[s][ni][2] = -1e30f;
                        if (c0 + 1 > rB) sacc[s][ni][3] = -1e30f;
                    }
                }
                float t0 = -1e30f, t1 = -1e30f;
                #pragma unroll
                for (int ni = 0; ni < 8; ni++) {
                    t0 = fmaxf(t0, fmaxf(sacc[s][ni][0], sacc[s][ni][1]));
                    t1 = fmaxf(t1, fmaxf(sacc[s][ni][2], sacc[s][ni][3]));
                }
                tmx[s][0] = t0; tmx[s][1] = t1;
            }
            // interleaved shuffle reduce: 4 independent chains, level by level
            #pragma unroll
            for (int d = 1; d <= 2; d <<= 1) {
                #pragma unroll
                for (int s = 0; s < 2; s++) {
                    tmx[s][0] = fmaxf(tmx[s][0],
                                      __shfl_xor_sync(0xffffffffu, tmx[s][0], d));
                    tmx[s][1] = fmaxf(tmx[s][1],
                                      __shfl_xor_sync(0xffffffffu, tmx[s][1], d));
                }
            }

            // ---- per-subtile: rescale, P = ex2(S-m) fp16x2, l via ones-MMA
            uint32_t pa[2][4][4];
            #pragma unroll
            for (int s = 0; s < 2; s++) {
                const float nm0 = fmaxf(mm[s][0], tmx[s][0]);
                const float nm1 = fmaxf(mm[s][1], tmx[s][1]);
                const float cr0 = exp2f(mm[s][0] - nm0), cr1 = exp2f(mm[s][1] - nm1);
                ll[s][0] *= cr0; ll[s][1] *= cr1;
                #pragma unroll
                for (int ni = 0; ni < 8; ni++) {
                    oacc[s][ni][0] *= cr0; oacc[s][ni][1] *= cr0;
                    oacc[s][ni][2] *= cr1; oacc[s][ni][3] *= cr1;
                }

                #pragma unroll
                for (int ks = 0; ks < 4; ks++) {
                    const int n0 = 2 * ks, n1 = 2 * ks + 1;
                    __half2 d;
                    d = __floats2half2_rn(sacc[s][n0][0] - nm0, sacc[s][n0][1] - nm0);
                    pa[s][ks][0] = h2exp2(*(uint32_t*)&d);
                    d = __floats2half2_rn(sacc[s][n0][2] - nm1, sacc[s][n0][3] - nm1);
                    pa[s][ks][1] = h2exp2(*(uint32_t*)&d);
                    d = __floats2half2_rn(sacc[s][n1][0] - nm0, sacc[s][n1][1] - nm0);
                    pa[s][ks][2] = h2exp2(*(uint32_t*)&d);
                    d = __floats2half2_rn(sacc[s][n1][2] - nm1, sacc[s][n1][3] - nm1);
                    pa[s][ks][3] = h2exp2(*(uint32_t*)&d);
                }

                float lacc[4] = {0.f, 0.f, 0.f, 0.f};
                #pragma unroll
                for (int ks = 0; ks < 4; ks++) mma16(lacc, pa[s][ks], onesb);
                ll[s][0] += lacc[0];
                ll[s][1] += lacc[2];
                mm[s][0] = nm0; mm[s][1] = nm1;
            }

            // ---- O += P @ V ----
            const int lt = lane >> 3, lr = lane & 7;
            #pragma unroll
            for (int ks = 0; ks < 4; ks++) {
                uint32_t vb[4][4];
                const int vrow = ks * 16 + (lt & 1) * 8 + lr;
                const int vcb  = (lt >> 1) * 8;
                #pragma unroll
                for (int d4 = 0; d4 < 4; d4++)
                    ldmx4t(vb[d4], sptr(Vs + vrow * VW + vcb + d4 * 16));
                #pragma unroll
                for (int s = 0; s < 2; s++) {
                    #pragma unroll
                    for (int d4 = 0; d4 < 4; d4++) {
                        mma16(oacc[s][2 * d4],     pa[s][ks], &vb[d4][0]);
                        mma16(oacc[s][2 * d4 + 1], pa[s][ks], &vb[d4][2]);
                    }
                }
            }
        }
    }

    // ---- epilogue: O/l -> g_att (fp16, σ-slot cols) ----
    #pragma unroll
    for (int s = 0; s < 2; s++) {
        const float inv0 = 1.f / ll[s][0], inv1 = 1.f / ll[s][1];
        const size_t ob = ((size_t)(b * SEQ + qr + s * 16 + g)) * DIM + h * HD;
        #pragma unroll
        for (int ni = 0; ni < 8; ni++) {
            const int c = ni * 8 + 2 * tig;
            *(__half2*)&g_att[ob + c] =
                __floats2half2_rn(oacc[s][ni][0] * inv0, oacc[s][ni][1] * inv0);
            *(__half2*)&g_att[ob + (size_t)8 * DIM + c] =
                __floats2half2_rn(oacc[s][ni][2] * inv1, oacc[s][ni][3] * inv1);
        }
    }
}

// ---------------------------------------------------------------------------
extern "C" void kernel_launch(void* const* d_in, const int* in_sizes, int n_in,
                              void* d_out, int out_size) {
    const float* x     = (const float*)d_in[0];
    const float* w_qkv = (const float*)d_in[1];
    const float* b_qkv = (const float*)d_in[2];
    const float* w_out = (const float*)d_in[3];
    const float* b_out = (const float*)d_in[4];
    float* out = (float*)d_out;

    __half* qkv; cudaGetSymbolAddress((void**)&qkv, g_qkv);
    __half* att; cudaGetSymbolAddress((void**)&att, g_att);
    __half* xa;  cudaGetSymbolAddress((void**)&xa,  g_xa);
    __half* wqT; cudaGetSymbolAddress((void**)&wqT, g_wqkvT);
    __half* woT; cudaGetSymbolAddress((void**)&woT, g_woutT);
    float*  bqp; cudaGetSymbolAddress((void**)&bqp, g_bqkvp);

    cudaFuncSetAttribute(hgemm<true>,
                         cudaFuncAttributeMaxDynamicSharedMemorySize, GEMM_SMEM);
    cudaFuncSetAttribute(hgemm<false>,
                         cudaFuncAttributeMaxDynamicSharedMemorySize, GEMM_SMEM);
    cudaFuncSetAttribute(attn_fp16,
                         cudaFuncAttributeMaxDynamicSharedMemorySize, ATTN_SMEM);

    // --- fused pre-pass ---
    prep_all<<<6144, 256>>>(x, w_qkv, w_out, b_qkv);

    // 1) QKV projection (fp16 mma, warp tile 64x64, 2 CTAs/SM)
    {
        dim3 grid(3 * DIM / 128, ROWS / 128);
        hgemm<true><<<grid, 128, GEMM_SMEM>>>(xa, wqT, bqp, qkv, 3 * DIM);
    }
    // 2) causal multi-head attention (log2-softmax, interleaved shuffles)
    {
        dim3 grid(SEQ / AQT, HEADS, BATCH);
        attn_fp16<<<grid, 128, ATTN_SMEM>>>();
    }
    // 3) output projection
    {
        dim3 grid(DIM / 128, ROWS / 128);
        hgemm<false><<<grid, 128, GEMM_SMEM>>>(att, woT, b_out, out, DIM);
    }
}

// round 16
// speedup vs baseline: 1.0376x; 1.0213x over previous
#include <cuda_runtime.h>
#include <cuda_fp16.h>
#include <cstdint>

#define BATCH 4
#define SEQ   2048
#define DIM   1024
#define HEADS 16
#define HD    64
#define ROWS (BATCH * SEQ)        // 8192

// Scratch (allocation-free rule: device globals), fp16 operand space
__device__ __half g_qkv[(size_t)ROWS * 3 * DIM];   // qkv, σ-permuted cols
__device__ __half g_att[(size_t)ROWS * DIM];       // attention out, σ-slot cols
__device__ __half g_xa[(size_t)ROWS * DIM];        // x, σ-permuted cols
__device__ __half g_wqkvT[(size_t)(3 * DIM) * DIM];// w_qkv^T, k+n σ-permuted
__device__ __half g_woutT[(size_t)DIM * DIM];      // w_out^T, k σ-permuted
__device__ float  g_bqkvp[3 * DIM];                // σ-permuted bias (fp32)

// ---------------------------------------------------------------------------
// helpers
// ---------------------------------------------------------------------------
__device__ __forceinline__ int sig16(int w) {          // w in [0,16)
    return 2 * (w >> 2) + (w & 1) + 8 * ((w >> 1) & 1);
}
__device__ __forceinline__ int sig(int s) { return (s & ~15) | sig16(s & 15); }

__device__ __forceinline__ void mma16(float* c, const uint32_t* a, const uint32_t* b) {
    asm volatile(
        "mma.sync.aligned.m16n8k16.row.col.f32.f16.f16.f32 "
        "{%0,%1,%2,%3}, {%4,%5,%6,%7}, {%8,%9}, {%0,%1,%2,%3};"
        : "+f"(c[0]), "+f"(c[1]), "+f"(c[2]), "+f"(c[3])
        : "r"(a[0]), "r"(a[1]), "r"(a[2]), "r"(a[3]), "r"(b[0]), "r"(b[1]));
}
__device__ __forceinline__ void ldmx4t(uint32_t* r, uint32_t addr) {
    asm volatile("ldmatrix.sync.aligned.m8n8.x4.trans.shared.b16 "
                 "{%0,%1,%2,%3}, [%4];"
                 : "=r"(r[0]), "=r"(r[1]), "=r"(r[2]), "=r"(r[3]) : "r"(addr));
}
__device__ __forceinline__ uint32_t h2exp2(uint32_t x) {
    uint32_t r;
    asm("ex2.approx.f16x2 %0, %1;" : "=r"(r) : "r"(x));
    return r;
}
__device__ __forceinline__ uint32_t sptr(const void* p) {
    return (uint32_t)__cvta_generic_to_shared(p);
}
// L1-bypass async copy: data is consumed only from smem, so caching in L1 is
// pure overhead; .cg routes L2 -> smem directly.
__device__ __forceinline__ void cp16(uint32_t s, const void* g) {
    asm volatile("cp.async.cg.shared.global [%0], [%1], 16;" :: "r"(s), "l"(g));
}
#define CP_COMMIT() asm volatile("cp.async.commit_group;")
#define CP_WAIT0()  asm volatile("cp.async.wait_group 0;")

// ---------------------------------------------------------------------------
// Fused pre-pass kernel
// ---------------------------------------------------------------------------
__device__ __forceinline__ void prep_w_tile(const float* __restrict__ src,
                                            __half* __restrict__ dst,
                                            int N, int kb, int nb, bool permn,
                                            int tid) {
    __shared__ float tile[32][33];
    const int tx = tid & 15, ty = tid >> 4;
    tile[ty][tx]           = src[(size_t)(kb + ty) * N + nb + tx];
    tile[ty][tx + 16]      = src[(size_t)(kb + ty) * N + nb + tx + 16];
    tile[ty + 16][tx]      = src[(size_t)(kb + ty + 16) * N + nb + tx];
    tile[ty + 16][tx + 16] = src[(size_t)(kb + ty + 16) * N + nb + tx + 16];
    __syncthreads();
    const int s  = 2 * tx;
    const int t0 = (s & 16) | sig16(s & 15);
    #pragma unroll
    for (int i = 0; i < 2; i++) {
        const int ny = ty + 16 * i;
        const int nn = permn ? ((ny & ~15) | sig16(ny & 15)) : ny;
        __half2 h = __floats2half2_rn(tile[t0][nn], tile[t0 + 1][nn]);
        *(__half2*)&dst[(size_t)(nb + ny) * DIM + kb + s] = h;
    }
}

__global__ __launch_bounds__(256)
void prep_all(const float* __restrict__ x, const float* __restrict__ wq,
              const float* __restrict__ wo, const float* __restrict__ bq) {
    const int bid = blockIdx.x;
    const int tid = threadIdx.x;
    if (bid < 2048) {
        const size_t base = ((size_t)bid * 256 + tid) * 16;
        float v[16];
        #pragma unroll
        for (int i = 0; i < 16; i += 4) *(float4*)&v[i] = *(const float4*)&x[base + i];
        __half2 h[8];
        #pragma unroll
        for (int u = 0; u < 4; u++) {
            h[2 * u]     = __floats2half2_rn(v[2 * u],     v[2 * u + 1]);
            h[2 * u + 1] = __floats2half2_rn(v[2 * u + 8], v[2 * u + 9]);
        }
        *(uint4*)&g_xa[base]     = *(uint4*)&h[0];
        *(uint4*)&g_xa[base + 8] = *(uint4*)&h[4];
        if (bid < 12) {
            const int s = bid * 256 + tid;
            g_bqkvp[s] = bq[sig(s)];
        }
    } else if (bid < 2048 + 3072) {
        const int b2 = bid - 2048;
        prep_w_tile(wq, g_wqkvT, 3 * DIM, (b2 & 31) * 32, (b2 >> 5) * 32, true, tid);
    } else {
        const int b3 = bid - 5120;
        prep_w_tile(wo, g_woutT, DIM, (b3 & 31) * 32, (b3 >> 5) * 32, false, tid);
    }
}

// ---------------------------------------------------------------------------
// FP16 MMA GEMM (R12 config): block 128x128, BK=64, 128 thr (4 warps 2x2),
// warp 64x64. 2 CTAs/SM. 1 barrier per k-tile. cp.async.cg fills.
// ---------------------------------------------------------------------------
#define GKW 80
#define GA_H (128 * GKW)
#define GSTG_H (2 * GA_H)
#define GEMM_SMEM (2 * GSTG_H * 2)          // 81920 B

__device__ __forceinline__ void gemm_load(__half* stage,
                                          const __half* __restrict__ A,
                                          const __half* __restrict__ B,
                                          int bm, int bn, int k0, int tid) {
    #pragma unroll
    for (int i = 0; i < 8; i++) {
        int t = tid + i * 128;              // 0..1023
        int row = t >> 3, c = t & 7;
        cp16(sptr(stage + row * GKW + c * 8), A + (size_t)(bm + row) * DIM + k0 + c * 8);
        cp16(sptr(stage + GA_H + row * GKW + c * 8), B + (size_t)(bn + row) * DIM + k0 + c * 8);
    }
}

template<bool HALF_OUT>
__global__ __launch_bounds__(128, 2)
void hgemm(const __half* __restrict__ A, const __half* __restrict__ B,
           const float* __restrict__ bias, void* __restrict__ Cv, int N) {
    extern __shared__ __half smh[];
    const int tid  = threadIdx.x;
    const int lane = tid & 31;
    const int wid  = tid >> 5;
    const int g    = lane >> 2;
    const int tig  = lane & 3;
    const int wm   = wid >> 1;          // 0..1
    const int wn   = wid & 1;           // 0..1
    const int bm   = blockIdx.y * 128;
    const int bn   = blockIdx.x * 128;

    float acc[4][8][4];
    #pragma unroll
    for (int mi = 0; mi < 4; mi++)
        #pragma unroll
        for (int ni = 0; ni < 8; ni++)
            #pragma unroll
            for (int j = 0; j < 4; j++) acc[mi][ni][j] = 0.f;

    constexpr int NT = DIM / 64;        // 16 k-tiles

    gemm_load(smh, A, B, bm, bn, 0, tid);
    CP_COMMIT();

    for (int t = 0; t < NT; t++) {
        CP_WAIT0();
        __syncthreads();
        if (t + 1 < NT) {
            gemm_load(smh + ((t + 1) & 1) * GSTG_H, A, B, bm, bn, (t + 1) * 64, tid);
            CP_COMMIT();
        }
        const __half* As = smh + (t & 1) * GSTG_H;
        const __half* Bs = As + GA_H;

        #pragma unroll
        for (int ks = 0; ks < 4; ks++) {
            const int co = ks * 16 + 4 * tig;
            uint32_t a[4][4], b[8][2];
            #pragma unroll
            for (int mi = 0; mi < 4; mi++) {
                const int m = wm * 64 + mi * 16 + g;
                uint2 lo = *(const uint2*)&As[m * GKW + co];
                uint2 hi = *(const uint2*)&As[(m + 8) * GKW + co];
                a[mi][0] = lo.x; a[mi][2] = lo.y;
                a[mi][1] = hi.x; a[mi][3] = hi.y;
            }
            #pragma unroll
            for (int ni = 0; ni < 8; ni++) {
                const int n = wn * 64 + ni * 8 + g;
                uint2 bb = *(const uint2*)&Bs[n * GKW + co];
                b[ni][0] = bb.x; b[ni][1] = bb.y;
            }
            #pragma unroll
            for (int mi = 0; mi < 4; mi++)
                #pragma unroll
                for (int ni = 0; ni < 8; ni++)
                    mma16(acc[mi][ni], a[mi], b[ni]);
        }
    }

    #pragma unroll
    for (int mi = 0; mi < 4; mi++) {
        const int r0 = bm + wm * 64 + mi * 16 + g;
        #pragma unroll
        for (int ni = 0; ni < 8; ni++) {
            const int col = bn + wn * 64 + ni * 8 + 2 * tig;
            const float b0 = bias[col], b1 = bias[col + 1];
            const float v00 = acc[mi][ni][0] + b0, v01 = acc[mi][ni][1] + b1;
            const float v10 = acc[mi][ni][2] + b0, v11 = acc[mi][ni][3] + b1;
            if (HALF_OUT) {
                __half* C = (__half*)Cv;
                *(__half2*)&C[(size_t)r0 * N + col]       = __floats2half2_rn(v00, v01);
                *(__half2*)&C[(size_t)(r0 + 8) * N + col] = __floats2half2_rn(v10, v11);
            } else {
                float* C = (float*)Cv;
                *(float2*)&C[(size_t)r0 * N + col]       = make_float2(v00, v01);
                *(float2*)&C[(size_t)(r0 + 8) * N + col] = make_float2(v10, v11);
            }
        }
    }
}

// ---------------------------------------------------------------------------
// FP16 MMA causal flash attention (exact R12 structure, .cg KV fills).
// Log2-domain softmax, ex2.approx.f16x2 P, l via ones-B MMA.
// grid = (SEQ/128, HEADS, BATCH), 128 thr, warp = 32 q rows, 2 CTAs/SM.
// smem halves: K[2][64][80] | V[2][64][72]  (38912 B)
// ---------------------------------------------------------------------------
#define AQT 128
#define KW  80
#define VW  72
#define KT_H (64 * KW)
#define VT_H (64 * VW)
#define ATTN_SMEM ((2 * KT_H + 2 * VT_H) * 2)   // 38912 B

__device__ __forceinline__ void attn_load_kv(__half* Ks, __half* Vs,
                                             int b, int h, int kt, int tid) {
    const size_t base = ((size_t)(b * SEQ + kt * 64)) * (3 * DIM) + DIM + h * HD;
    #pragma unroll
    for (int i = 0; i < 4; i++) {
        int t = tid + i * 128;              // 0..511
        int row = t >> 3, c = t & 7;
        const __half* src = &g_qkv[base + (size_t)row * 3 * DIM + c * 8];
        cp16(sptr(Ks + row * KW + c * 8), src);
        cp16(sptr(Vs + row * VW + c * 8), src + DIM);
    }
}

__global__ __launch_bounds__(128)
void attn_fp16() {
    extern __shared__ __half smh[];
    __half* Kb[2] = { smh, smh + KT_H };
    __half* Vb[2] = { smh + 2 * KT_H, smh + 2 * KT_H + VT_H };

    const int qt   = gridDim.x - 1 - blockIdx.x;   // longest-first scheduling
    const int h    = blockIdx.y;
    const int b    = blockIdx.z;
    const int tid  = threadIdx.x;
    const int lane = tid & 31;
    const int wid  = tid >> 5;
    const int g    = lane >> 2;
    const int tig  = lane & 3;

    const int qr  = qt * AQT + wid * 32;
    const int nkt = qt * 2 + 2;

    attn_load_kv(Kb[0], Vb[0], b, h, 0, tid);
    CP_COMMIT();

    // q scale folds 1/sqrt(64) AND log2(e): softmax runs in base-2 domain
    const __half2 qsc = __float2half2_rn(0.125f * 1.44269504f);
    uint32_t qf[2][4][4];
    #pragma unroll
    for (int s = 0; s < 2; s++) {
        const size_t r0 = ((size_t)(b * SEQ + qr + s * 16 + g)) * (3 * DIM) + h * HD;
        const size_t r1 = r0 + (size_t)8 * 3 * DIM;
        #pragma unroll
        for (int ks = 0; ks < 4; ks++) {
            uint2 lo = *(const uint2*)&g_qkv[r0 + ks * 16 + 4 * tig];
            uint2 hi = *(const uint2*)&g_qkv[r1 + ks * 16 + 4 * tig];
            __half2 t;
            t = __hmul2(*(__half2*)&lo.x, qsc); qf[s][ks][0] = *(uint32_t*)&t;
            t = __hmul2(*(__half2*)&hi.x, qsc); qf[s][ks][1] = *(uint32_t*)&t;
            t = __hmul2(*(__half2*)&lo.y, qsc); qf[s][ks][2] = *(uint32_t*)&t;
            t = __hmul2(*(__half2*)&hi.y, qsc); qf[s][ks][3] = *(uint32_t*)&t;
        }
    }

    float oacc[2][8][4];
    #pragma unroll
    for (int s = 0; s < 2; s++)
        #pragma unroll
        for (int ni = 0; ni < 8; ni++)
            #pragma unroll
            for (int j = 0; j < 4; j++) oacc[s][ni][j] = 0.f;
    float mm[2][2] = {{-1e30f, -1e30f}, {-1e30f, -1e30f}};
    float ll[2][2] = {{0.f, 0.f}, {0.f, 0.f}};
    const uint32_t ones2 = 0x3C003C00u;            // half2(1,1)
    const uint32_t onesb[2] = { ones2, ones2 };

    for (int kt = 0; kt < nkt; kt++) {
        CP_WAIT0();
        __syncthreads();
        if (kt + 1 < nkt) {
            attn_load_kv(Kb[(kt + 1) & 1], Vb[(kt + 1) & 1], b, h, kt + 1, tid);
            CP_COMMIT();
        }
        const __half* Ks = Kb[kt & 1];
        const __half* Vs = Vb[kt & 1];

        const bool active = (kt * 64 <= qr + 31);
        if (active) {
            const bool diag = ((kt + 1) * 64 > qr);

            // ---- S = Q K^T (log2-e domain): K frags shared by both subtiles
            float sacc[2][8][4];
            #pragma unroll
            for (int s = 0; s < 2; s++)
                #pragma unroll
                for (int ni = 0; ni < 8; ni++)
                    #pragma unroll
                    for (int j = 0; j < 4; j++) sacc[s][ni][j] = 0.f;

            #pragma unroll
            for (int ks = 0; ks < 4; ks++) {
                const int co = ks * 16 + 4 * tig;
                #pragma unroll
                for (int ni = 0; ni < 8; ni++) {
                    uint2 bb = *(const uint2*)&Ks[(ni * 8 + g) * KW + co];
                    uint32_t bfr[2] = { bb.x, bb.y };
                    mma16(sacc[0][ni], qf[0][ks], bfr);
                    mma16(sacc[1][ni], qf[1][ks], bfr);
                }
            }

            // ---- per-subtile: mask, max, P = ex2(S-m) in fp16x2, l via MMA
            uint32_t pa[2][4][4];
            #pragma unroll
            for (int s = 0; s < 2; s++) {
                const int rA = qr + s * 16 + g, rB = rA + 8;
                if (diag) {
                    #pragma unroll
                    for (int ni = 0; ni < 8; ni++) {
                        const int c0 = kt * 64 + ni * 8 + 2 * tig;
                        if (c0 > rA)     sacc[s][ni][0] = -1e30f;
                        if (c0 + 1 > rA) sacc[s][ni][1] = -1e30f;
                        if (c0 > rB)     sacc[s][ni][2] = -1e30f;
                        if (c0 + 1 > rB) sacc[s][ni][3] = -1e30f;
                    }
                }

                float t0 = -1e30f, t1 = -1e30f;
                #pragma unroll
                for (int ni = 0; ni < 8; ni++) {
                    t0 = fmaxf(t0, fmaxf(sacc[s][ni][0], sacc[s][ni][1]));
                    t1 = fmaxf(t1, fmaxf(sacc[s][ni][2], sacc[s][ni][3]));
                }
                t0 = fmaxf(t0, __shfl_xor_sync(0xffffffffu, t0, 1));
                t0 = fmaxf(t0, __shfl_xor_sync(0xffffffffu, t0, 2));
                t1 = fmaxf(t1, __shfl_xor_sync(0xffffffffu, t1, 1));
                t1 = fmaxf(t1, __shfl_xor_sync(0xffffffffu, t1, 2));

                const float nm0 = fmaxf(mm[s][0], t0), nm1 = fmaxf(mm[s][1], t1);
                const float cr0 = exp2f(mm[s][0] - nm0), cr1 = exp2f(mm[s][1] - nm1);
                ll[s][0] *= cr0; ll[s][1] *= cr1;
                #pragma unroll
                for (int ni = 0; ni < 8; ni++) {
                    oacc[s][ni][0] *= cr0; oacc[s][ni][1] *= cr0;
                    oacc[s][ni][2] *= cr1; oacc[s][ni][3] *= cr1;
                }

                #pragma unroll
                for (int ks = 0; ks < 4; ks++) {
                    const int n0 = 2 * ks, n1 = 2 * ks + 1;
                    __half2 d;
                    d = __floats2half2_rn(sacc[s][n0][0] - nm0, sacc[s][n0][1] - nm0);
                    pa[s][ks][0] = h2exp2(*(uint32_t*)&d);
                    d = __floats2half2_rn(sacc[s][n0][2] - nm1, sacc[s][n0][3] - nm1);
                    pa[s][ks][1] = h2exp2(*(uint32_t*)&d);
                    d = __floats2half2_rn(sacc[s][n1][0] - nm0, sacc[s][n1][1] - nm0);
                    pa[s][ks][2] = h2exp2(*(uint32_t*)&d);
                    d = __floats2half2_rn(sacc[s][n1][2] - nm1, sacc[s][n1][3] - nm1);
                    pa[s][ks][3] = h2exp2(*(uint32_t*)&d);
                }

                // l += P @ ones  (fp32 accum)
                float lacc[4] = {0.f, 0.f, 0.f, 0.f};
                #pragma unroll
                for (int ks = 0; ks < 4; ks++) mma16(lacc, pa[s][ks], onesb);
                ll[s][0] += lacc[0];
                ll[s][1] += lacc[2];
                mm[s][0] = nm0; mm[s][1] = nm1;
            }

            // ---- O += P @ V ----
            const int lt = lane >> 3, lr = lane & 7;
            #pragma unroll
            for (int ks = 0; ks < 4; ks++) {
                uint32_t vb[4][4];
                const int vrow = ks * 16 + (lt & 1) * 8 + lr;
                const int vcb  = (lt >> 1) * 8;
                #pragma unroll
                for (int d4 = 0; d4 < 4; d4++)
                    ldmx4t(vb[d4], sptr(Vs + vrow * VW + vcb + d4 * 16));
                #pragma unroll
                for (int s = 0; s < 2; s++) {
                    #pragma unroll
                    for (int d4 = 0; d4 < 4; d4++) {
                        mma16(oacc[s][2 * d4],     pa[s][ks], &vb[d4][0]);
                        mma16(oacc[s][2 * d4 + 1], pa[s][ks], &vb[d4][2]);
                    }
                }
            }
        }
    }

    // ---- epilogue: O/l -> g_att (fp16, σ-slot cols) ----
    #pragma unroll
    for (int s = 0; s < 2; s++) {
        const float inv0 = 1.f / ll[s][0], inv1 = 1.f / ll[s][1];
        const size_t ob = ((size_t)(b * SEQ + qr + s * 16 + g)) * DIM + h * HD;
        #pragma unroll
        for (int ni = 0; ni < 8; ni++) {
            const int c = ni * 8 + 2 * tig;
            *(__half2*)&g_att[ob + c] =
                __floats2half2_rn(oacc[s][ni][0] * inv0, oacc[s][ni][1] * inv0);
            *(__half2*)&g_att[ob + (size_t)8 * DIM + c] =
                __floats2half2_rn(oacc[s][ni][2] * inv1, oacc[s][ni][3] * inv1);
        }
    }
}

// ---------------------------------------------------------------------------
extern "C" void kernel_launch(void* const* d_in, const int* in_sizes, int n_in,
                              void* d_out, int out_size) {
    const float* x     = (const float*)d_in[0];
    const float* w_qkv = (const float*)d_in[1];
    const float* b_qkv = (const float*)d_in[2];
    const float* w_out = (const float*)d_in[3];
    const float* b_out = (const float*)d_in[4];
    float* out = (float*)d_out;

    __half* qkv; cudaGetSymbolAddress((void**)&qkv, g_qkv);
    __half* att; cudaGetSymbolAddress((void**)&att, g_att);
    __half* xa;  cudaGetSymbolAddress((void**)&xa,  g_xa);
    __half* wqT; cudaGetSymbolAddress((void**)&wqT, g_wqkvT);
    __half* woT; cudaGetSymbolAddress((void**)&woT, g_woutT);
    float*  bqp; cudaGetSymbolAddress((void**)&bqp, g_bqkvp);

    cudaFuncSetAttribute(hgemm<true>,
                         cudaFuncAttributeMaxDynamicSharedMemorySize, GEMM_SMEM);
    cudaFuncSetAttribute(hgemm<false>,
                         cudaFuncAttributeMaxDynamicSharedMemorySize, GEMM_SMEM);
    cudaFuncSetAttribute(attn_fp16,
                         cudaFuncAttributeMaxDynamicSharedMemorySize, ATTN_SMEM);

    // --- fused pre-pass ---
    prep_all<<<6144, 256>>>(x, w_qkv, w_out, b_qkv);

    // 1) QKV projection (fp16 mma, warp tile 64x64, 2 CTAs/SM, .cg fills)
    {
        dim3 grid(3 * DIM / 128, ROWS / 128);
        hgemm<true><<<grid, 128, GEMM_SMEM>>>(xa, wqT, bqp, qkv, 3 * DIM);
    }
    // 2) causal multi-head attention (log2-softmax, ex2.f16x2, l via MMA)
    {
        dim3 grid(SEQ / AQT, HEADS, BATCH);
        attn_fp16<<<grid, 128, ATTN_SMEM>>>();
    }
    // 3) output projection
    {
        dim3 grid(DIM / 128, ROWS / 128);
        hgemm<false><<<grid, 128, GEMM_SMEM>>>(att, woT, b_out, out, DIM);
    }
}